// round 1
// baseline (speedup 1.0000x reference)
#include <cuda_runtime.h>
#include <math.h>

#define B_SZ   2048
#define T_SZ   512
#define D_IN   64
#define H_SZ   128
#define D_OUT  64
#define M_TILE 16
#define NTHREADS 128
#define NSTEPS (T_SZ - 1)

// Shared memory layout (floats):
//  [0      .. 16384)  Whh_t  (k-major: Whh_t[k*H+j] = W_hh[j*H+k])
//  [16384  .. 32768)  W1_t
//  [32768  .. 49152)  W2_t   (also reused post-loop for W_out_t, 8192 floats)
//  [49152  .. 51200)  buf0   [16][128]
//  [51200  .. 53248)  buf1   [16][128]
//  [53248  .. 53376)  v_s
//  [53376  .. 53504)  c_s
//  [53504  .. 53632)  b1_s
//  [53632  .. 53760)  b2_s
//  [53760  .. 53776)  xs
#define SMEM_FLOATS 53776
#define SMEM_BYTES  (SMEM_FLOATS * 4)

__device__ __forceinline__ void gemm_acc(const float* __restrict__ Wt,
                                         const float* __restrict__ bufp,
                                         int rbase, int j0, float acc[4][4]) {
#pragma unroll 8
    for (int k = 0; k < H_SZ; k += 4) {
        const float4 w0 = *reinterpret_cast<const float4*>(Wt + (k + 0) * H_SZ + j0);
        const float4 w1 = *reinterpret_cast<const float4*>(Wt + (k + 1) * H_SZ + j0);
        const float4 w2 = *reinterpret_cast<const float4*>(Wt + (k + 2) * H_SZ + j0);
        const float4 w3 = *reinterpret_cast<const float4*>(Wt + (k + 3) * H_SZ + j0);
#pragma unroll
        for (int ri = 0; ri < 4; ri++) {
            const float4 a = *reinterpret_cast<const float4*>(bufp + (rbase + ri) * H_SZ + k);
            acc[ri][0] = fmaf(a.x, w0.x, acc[ri][0]);
            acc[ri][1] = fmaf(a.x, w0.y, acc[ri][1]);
            acc[ri][2] = fmaf(a.x, w0.z, acc[ri][2]);
            acc[ri][3] = fmaf(a.x, w0.w, acc[ri][3]);
            acc[ri][0] = fmaf(a.y, w1.x, acc[ri][0]);
            acc[ri][1] = fmaf(a.y, w1.y, acc[ri][1]);
            acc[ri][2] = fmaf(a.y, w1.z, acc[ri][2]);
            acc[ri][3] = fmaf(a.y, w1.w, acc[ri][3]);
            acc[ri][0] = fmaf(a.z, w2.x, acc[ri][0]);
            acc[ri][1] = fmaf(a.z, w2.y, acc[ri][1]);
            acc[ri][2] = fmaf(a.z, w2.z, acc[ri][2]);
            acc[ri][3] = fmaf(a.z, w2.w, acc[ri][3]);
            acc[ri][0] = fmaf(a.w, w3.x, acc[ri][0]);
            acc[ri][1] = fmaf(a.w, w3.y, acc[ri][1]);
            acc[ri][2] = fmaf(a.w, w3.z, acc[ri][2]);
            acc[ri][3] = fmaf(a.w, w3.w, acc[ri][3]);
        }
    }
}

__device__ __forceinline__ void stage4(float* __restrict__ bufp, int rbase, int j0,
                                       const float v[4][4]) {
#pragma unroll
    for (int ri = 0; ri < 4; ri++) {
        *reinterpret_cast<float4*>(bufp + (rbase + ri) * H_SZ + j0) =
            make_float4(v[ri][0], v[ri][1], v[ri][2], v[ri][3]);
    }
}

__device__ __forceinline__ float silu_f(float v) {
    return v / (1.0f + expf(-v));
}

// out = f(in) = silu(in @ W1^T + b1) @ W2^T + b2
__device__ __forceinline__ void feval(const float in[4][4], float out[4][4],
                                      const float* __restrict__ W1t,
                                      const float* __restrict__ W2t,
                                      const float* __restrict__ b1s,
                                      const float* __restrict__ b2s,
                                      float* __restrict__ buf0,
                                      float* __restrict__ buf1,
                                      int& p, int rbase, int j0) {
    float* bp = p ? buf1 : buf0;
    stage4(bp, rbase, j0, in);
    __syncthreads();

    float z[4][4];
    const float4 bb1 = *reinterpret_cast<const float4*>(b1s + j0);
#pragma unroll
    for (int ri = 0; ri < 4; ri++) {
        z[ri][0] = bb1.x; z[ri][1] = bb1.y; z[ri][2] = bb1.z; z[ri][3] = bb1.w;
    }
    gemm_acc(W1t, bp, rbase, j0, z);
#pragma unroll
    for (int ri = 0; ri < 4; ri++)
#pragma unroll
        for (int c = 0; c < 4; c++)
            z[ri][c] = silu_f(z[ri][c]);

    p ^= 1;
    bp = p ? buf1 : buf0;
    stage4(bp, rbase, j0, z);
    __syncthreads();

    const float4 bb2 = *reinterpret_cast<const float4*>(b2s + j0);
#pragma unroll
    for (int ri = 0; ri < 4; ri++) {
        out[ri][0] = bb2.x; out[ri][1] = bb2.y; out[ri][2] = bb2.z; out[ri][3] = bb2.w;
    }
    gemm_acc(W2t, bp, rbase, j0, out);
    p ^= 1;
}

__global__ void __launch_bounds__(NTHREADS, 1)
rnnode_kernel(const float* __restrict__ x, const float* __restrict__ span,
              const float* __restrict__ W_emb, const float* __restrict__ b_emb,
              const float* __restrict__ W_ih, const float* __restrict__ b_ih,
              const float* __restrict__ W_hh, const float* __restrict__ b_hh,
              const float* __restrict__ W1, const float* __restrict__ b1,
              const float* __restrict__ W2, const float* __restrict__ b2,
              const float* __restrict__ W_out, const float* __restrict__ b_out,
              float* __restrict__ out) {
    extern __shared__ float sm[];
    float* Whh_t = sm;
    float* W1t   = sm + 16384;
    float* W2t   = sm + 32768;
    float* buf0  = sm + 49152;
    float* buf1  = sm + 51200;
    float* v_s   = sm + 53248;
    float* c_s   = sm + 53376;
    float* b1_s  = sm + 53504;
    float* b2_s  = sm + 53632;
    float* xs    = sm + 53760;

    const int tid = threadIdx.x;
    const int b0  = blockIdx.x * M_TILE;

    // Load weights transposed to k-major (one-time; STS conflicts are amortized).
    for (int i = tid; i < H_SZ * H_SZ; i += NTHREADS) {
        const int j = i >> 7, k = i & 127;
        Whh_t[k * H_SZ + j] = W_hh[i];
        W1t[k * H_SZ + j]   = W1[i];
        W2t[k * H_SZ + j]   = W2[i];
    }
    // Fold input path: u[b,t,:] = x[b,t]*v + c, with c absorbing b_ih + b_hh.
    if (tid < H_SZ) {
        float vv = 0.0f, cc = 0.0f;
        for (int d = 0; d < D_IN; d++) {
            const float w = W_ih[tid * D_IN + d];
            vv = fmaf(w, W_emb[d], vv);
            cc = fmaf(w, b_emb[d], cc);
        }
        v_s[tid]  = vv;
        c_s[tid]  = cc + b_ih[tid] + b_hh[tid];
        b1_s[tid] = b1[tid];
        b2_s[tid] = b2[tid];
    }
    __syncthreads();

    const int rg    = tid >> 5;      // warp id 0..3 -> row group
    const int lane  = tid & 31;
    const int rbase = rg * 4;        // rows rbase..rbase+3 of the 16-row tile
    const int j0    = lane * 4;      // cols j0..j0+3

    float h[4][4];
#pragma unroll
    for (int ri = 0; ri < 4; ri++)
#pragma unroll
        for (int c = 0; c < 4; c++) h[ri][c] = 0.0f;

    int p = 0;

    for (int t = 0; t < NSTEPS; t++) {
        const float dt  = __ldg(span + t + 1) - __ldg(span + t);
        const float dt3 = dt * (1.0f / 3.0f);

        // ---- RNN jump: h = tanh(x*v + c + h @ W_hh^T) ----
        float* bp = p ? buf1 : buf0;
        stage4(bp, rbase, j0, h);
        if (tid < M_TILE) xs[tid] = x[(size_t)(b0 + tid) * T_SZ + t];
        __syncthreads();

        float acc[4][4];
        {
            const float4 vv = *reinterpret_cast<const float4*>(v_s + j0);
            const float4 cc = *reinterpret_cast<const float4*>(c_s + j0);
#pragma unroll
            for (int ri = 0; ri < 4; ri++) {
                const float xv = xs[rbase + ri];
                acc[ri][0] = fmaf(xv, vv.x, cc.x);
                acc[ri][1] = fmaf(xv, vv.y, cc.y);
                acc[ri][2] = fmaf(xv, vv.z, cc.z);
                acc[ri][3] = fmaf(xv, vv.w, cc.w);
            }
        }
        gemm_acc(Whh_t, bp, rbase, j0, acc);
        p ^= 1;
#pragma unroll
        for (int ri = 0; ri < 4; ri++)
#pragma unroll
            for (int c = 0; c < 4; c++) h[ri][c] = tanhf(acc[ri][c]);

        // ---- RK4 (3/8 rule): k1..k4 ----
        float k1v[4][4], k2v[4][4], kv[4][4], y[4][4], ksum[4][4];

        feval(h, k1v, W1t, W2t, b1_s, b2_s, buf0, buf1, p, rbase, j0);
#pragma unroll
        for (int ri = 0; ri < 4; ri++)
#pragma unroll
            for (int c = 0; c < 4; c++)
                y[ri][c] = fmaf(dt3, k1v[ri][c], h[ri][c]);

        feval(y, k2v, W1t, W2t, b1_s, b2_s, buf0, buf1, p, rbase, j0);
#pragma unroll
        for (int ri = 0; ri < 4; ri++)
#pragma unroll
            for (int c = 0; c < 4; c++)
                y[ri][c] = fmaf(dt, k2v[ri][c], fmaf(-dt3, k1v[ri][c], h[ri][c]));

        feval(y, kv, W1t, W2t, b1_s, b2_s, buf0, buf1, p, rbase, j0);  // k3
#pragma unroll
        for (int ri = 0; ri < 4; ri++)
#pragma unroll
            for (int c = 0; c < 4; c++) {
                ksum[ri][c] = k1v[ri][c] + 3.0f * (k2v[ri][c] + kv[ri][c]);
                y[ri][c] = fmaf(dt, k1v[ri][c] - k2v[ri][c] + kv[ri][c], h[ri][c]);
            }

        feval(y, kv, W1t, W2t, b1_s, b2_s, buf0, buf1, p, rbase, j0);  // k4
        const float dt8 = dt * 0.125f;
#pragma unroll
        for (int ri = 0; ri < 4; ri++)
#pragma unroll
            for (int c = 0; c < 4; c++)
                h[ri][c] = fmaf(dt8, ksum[ri][c] + kv[ri][c], h[ri][c]);
    }

    // ---- out = h @ W_out^T + b_out ----
    __syncthreads();  // all GEMM readers done before W1t region is reused
    // W_out_t[k*64 + j] into W1t region
    for (int i = tid; i < D_OUT * H_SZ; i += NTHREADS) {
        const int j = i >> 7, k = i & 127;
        W1t[k * D_OUT + j] = W_out[i];
    }
    float* bp = p ? buf1 : buf0;
    stage4(bp, rbase, j0, h);
    __syncthreads();

    const int jo = lane * 2;  // 2 output cols per lane (64 cols)
#pragma unroll
    for (int ri = 0; ri < 4; ri++) {
        float o0 = __ldg(b_out + jo);
        float o1 = __ldg(b_out + jo + 1);
        const float* br = bp + (rbase + ri) * H_SZ;
#pragma unroll 16
        for (int k = 0; k < H_SZ; k++) {
            const float a = br[k];
            const float2 w = *reinterpret_cast<const float2*>(W1t + k * D_OUT + jo);
            o0 = fmaf(a, w.x, o0);
            o1 = fmaf(a, w.y, o1);
        }
        float2 res = make_float2(o0, o1);
        *reinterpret_cast<float2*>(out + (size_t)(b0 + rbase + ri) * D_OUT + jo) = res;
    }
}

extern "C" void kernel_launch(void* const* d_in, const int* in_sizes, int n_in,
                              void* d_out, int out_size) {
    const float* x     = (const float*)d_in[0];
    const float* span  = (const float*)d_in[1];
    const float* W_emb = (const float*)d_in[2];
    const float* b_emb = (const float*)d_in[3];
    const float* W_ih  = (const float*)d_in[4];
    const float* b_ih  = (const float*)d_in[5];
    const float* W_hh  = (const float*)d_in[6];
    const float* b_hh  = (const float*)d_in[7];
    const float* W1    = (const float*)d_in[8];
    const float* b1    = (const float*)d_in[9];
    const float* W2    = (const float*)d_in[10];
    const float* b2    = (const float*)d_in[11];
    const float* W_out = (const float*)d_in[12];
    const float* b_out = (const float*)d_in[13];
    float* out = (float*)d_out;

    cudaFuncSetAttribute(rnnode_kernel,
                         cudaFuncAttributeMaxDynamicSharedMemorySize, SMEM_BYTES);
    rnnode_kernel<<<B_SZ / M_TILE, NTHREADS, SMEM_BYTES>>>(
        x, span, W_emb, b_emb, W_ih, b_ih, W_hh, b_hh,
        W1, b1, W2, b2, W_out, b_out, out);
}